// round 12
// baseline (speedup 1.0000x reference)
#include <cuda_runtime.h>
#include <cuda_fp16.h>
#include <cstdint>

// ---------------------------------------------------------------------------
// Problem constants
// ---------------------------------------------------------------------------
static constexpr int M_TOTAL = 8192;      // 4 * 2048
static constexpr int N_TOTAL = 11008;
static constexpr int K_TOTAL = 4096;

static constexpr int BM = 64;
static constexpr int BN = 256;
static constexpr int BK = 64;                 // fp16 -> 128 B per row
static constexpr int KITERS = K_TOTAL / BK;   // 64
static constexpr int THREADS = 128;           // 4 warps, 2 CTAs per SM

static constexpr int A_SUB = BM * BK * 2;     // 8 KB per kiter sub-buffer
static constexpr int B_STAGE = BN * BK * 2;   // 32 KB
static constexpr int SMEM_BYTES = 4 * A_SUB + 2 * B_STAGE + 1024;  // 99328 -> 2 CTAs/SM

static constexpr int PID_N = N_TOTAL / BN;    // 43
static constexpr int GROUP_M = 8;             // CTA rasterization group
static constexpr int N_TILES = (M_TOTAL / BM) * PID_N;   // 5504

static constexpr int X_BLOCKS = 33554432 / 4 / 256;   // 32768 (float4 granules)
static constexpr int W_BLOCKS = 45088768 / 4 / 256;   // 44032 (int4 granules)

// ---------------------------------------------------------------------------
// Scratch (device globals: allocation-free)
// ---------------------------------------------------------------------------
__device__ __half g_xh[(size_t)M_TOTAL * K_TOTAL];   // 67 MB, fp16 x
__device__ __half g_wh[(size_t)N_TOTAL * K_TOTAL];   // 90 MB, fp16 dequant W

__constant__ float c_nf4[16] = {
    -1.0f, -0.6961928009986877f, -0.5250730514526367f, -0.39491748809814453f,
    -0.28444138169288635f, -0.18477343022823334f, -0.09105003625154495f, 0.0f,
    0.07958029955625534f, 0.16093020141124725f, 0.24611230194568634f,
    0.33791524171829224f, 0.44070982933044434f, 0.5626170039176941f,
    0.7229568362236023f, 1.0f};

// ---------------------------------------------------------------------------
// Helpers (baseline PTX only; sm_103 virtual target has no tcgen05)
// ---------------------------------------------------------------------------
__device__ __forceinline__ uint32_t smem_u32(const void* p) {
    uint32_t a;
    asm("{ .reg .u64 t; cvta.to.shared.u64 t, %1; cvt.u32.u64 %0, t; }" : "=r"(a) : "l"(p));
    return a;
}

__device__ __forceinline__ void cp16(uint32_t dst, const void* src) {
    asm volatile("cp.async.cg.shared.global [%0], [%1], 16;" :: "r"(dst), "l"(src));
}
__device__ __forceinline__ void cp_commit() {
    asm volatile("cp.async.commit_group;" ::: "memory");
}
template <int N>
__device__ __forceinline__ void cp_wait() {
    asm volatile("cp.async.wait_group %0;" :: "n"(N) : "memory");
}

__device__ __forceinline__ void ldsm4(uint32_t* r, uint32_t addr) {
    asm volatile("ldmatrix.sync.aligned.m8n8.x4.shared.b16 {%0,%1,%2,%3}, [%4];"
                 : "=r"(r[0]), "=r"(r[1]), "=r"(r[2]), "=r"(r[3]) : "r"(addr));
}

__device__ __forceinline__ void mma_f16(float* c, const uint32_t* a,
                                        uint32_t b0, uint32_t b1) {
    asm volatile(
        "mma.sync.aligned.m16n8k16.row.col.f32.f16.f16.f32 "
        "{%0,%1,%2,%3}, {%4,%5,%6,%7}, {%8,%9}, {%0,%1,%2,%3};"
        : "+f"(c[0]), "+f"(c[1]), "+f"(c[2]), "+f"(c[3])
        : "r"(a[0]), "r"(a[1]), "r"(a[2]), "r"(a[3]), "r"(b0), "r"(b1));
}

// SW128 swizzle on (row*128 + colb)
#define SWZ(row, colb) ((uint32_t)(row) * 128u + ((uint32_t)(colb) ^ ((((uint32_t)(row)) & 7u) << 4)))

// grouped rasterization: consecutive tile ids share B (same n-column) within
// groups of 8 m-tiles -> per-wave working set stays inside L2
__device__ __forceinline__ void tile_coords(int t, int& m0, int& n0) {
    int group = t / (GROUP_M * PID_N);
    int local = t % (GROUP_M * PID_N);
    int pid_m = group * GROUP_M + (local & (GROUP_M - 1));
    int pid_n = local >> 3;                    // GROUP_M = 8
    m0 = pid_m * BM;
    n0 = pid_n * BN;
}

// ---------------------------------------------------------------------------
// Kernel 1 (fused prepass): x -> fp16, NF4 dequant W -> fp16
// ---------------------------------------------------------------------------
__global__ void __launch_bounds__(256) prepass_kernel(const float* __restrict__ x,
                                                      const int* __restrict__ q,
                                                      const float* __restrict__ sc) {
    if (blockIdx.x < X_BLOCKS) {
        size_t i = (size_t)blockIdx.x * 256 + threadIdx.x;   // float4 index
        float4 v = reinterpret_cast<const float4*>(x)[i];
        __half2 h0 = __floats2half2_rn(v.x, v.y);
        __half2 h1 = __floats2half2_rn(v.z, v.w);
        uint2 o = make_uint2(*reinterpret_cast<uint32_t*>(&h0),
                             *reinterpret_cast<uint32_t*>(&h1));
        reinterpret_cast<uint2*>(g_xh)[i] = o;
    } else {
        float tv = c_nf4[threadIdx.x & 15];                  // lane l holds nf4[l&15]
        size_t i = (size_t)(blockIdx.x - X_BLOCKS) * 256 + threadIdx.x; // int4 pack idx
        int4 qq = reinterpret_cast<const int4*>(q)[i];
        float s = __ldg(sc + (i >> 5));                      // 128-elem group = 32 packs
        float wx = __shfl_sync(0xffffffffu, tv, qq.x & 15) * s;
        float wy = __shfl_sync(0xffffffffu, tv, qq.y & 15) * s;
        float wz = __shfl_sync(0xffffffffu, tv, qq.z & 15) * s;
        float ww = __shfl_sync(0xffffffffu, tv, qq.w & 15) * s;
        __half2 h0 = __floats2half2_rn(wx, wy);
        __half2 h1 = __floats2half2_rn(wz, ww);
        uint2 o = make_uint2(*reinterpret_cast<uint32_t*>(&h0),
                             *reinterpret_cast<uint32_t*>(&h1));
        reinterpret_cast<uint2*>(g_wh)[i] = o;
    }
}

// ---------------------------------------------------------------------------
// Kernel 2: persistent mma.sync fp16 GEMM.
// 128 threads = 4 warps, warp tile 64x64 (1M x 4N), 2 CTAs per SM.
// A: 4 sub-buffers in 2-kiter chunks -> __syncthreads at even gi only.
// B: 2 warp-private stages.  Single cp_wait<0> + single commit per kiter.
// NEW vs R8: the per-kiter cp.async bursts (16 B + 8 A chunks, asm volatile ->
// ptxas cannot reorder them) are hand-interleaved into the ks=0/1/2 MMA
// phases in <=10-op fragments, so each fragment's issue time is covered by
// the >=256-cycle tensor backlog queued by the preceding MMA block.
// ---------------------------------------------------------------------------
__device__ __forceinline__ void load_A(int kiter, int sub, int m0,
                                       uint32_t a_smem, int tid) {
    const __half* asrc = g_xh + (size_t)m0 * K_TOTAL + kiter * BK;
    uint32_t adst = a_smem + sub * A_SUB;
#pragma unroll
    for (int it = 0; it < 4; it++) {                 // 512 16B chunks / 128 thr
        int idx = tid + it * THREADS;
        int r = idx >> 3, ch = idx & 7;
        cp16(adst + SWZ(r, ch * 16), asrc + (size_t)r * K_TOTAL + ch * 8);
    }
}

// warp-sliced B chunk range [it0, it1): warp w owns rows [64w, 64w+64)
__device__ __forceinline__ void load_B_part(const __half* bsrc, uint32_t bdst,
                                            int wid, int lane, int it0, int it1) {
#pragma unroll
    for (int it = it0; it < it1; it++) {             // 512 chunks / 32 lanes
        int cc = lane + it * 32;
        int r = wid * 64 + (cc >> 3), ch = cc & 7;
        cp16(bdst + SWZ(r, ch * 16), bsrc + (size_t)r * K_TOTAL + ch * 8);
    }
}

__device__ __forceinline__ void ldsm_phase(uint32_t a[4][4], uint32_t b[4][4],
                                           uint32_t abase, uint32_t bbase, int ks,
                                           uint32_t arow0, uint32_t acolq,
                                           uint32_t brow0, uint32_t bcolq, uint32_t xorv) {
    uint32_t colA = ((uint32_t)(ks * 32) + acolq) ^ xorv;
    uint32_t colB = ((uint32_t)(ks * 32) + bcolq) ^ xorv;
#pragma unroll
    for (int mt = 0; mt < 4; mt++)
        ldsm4(a[mt], abase + (arow0 + mt * 16) * 128 + colA);
#pragma unroll
    for (int nb = 0; nb < 4; nb++)
        ldsm4(b[nb], bbase + (brow0 + nb * 16) * 128 + colB);
}

__device__ __forceinline__ void mma_phase(float c[4][8][4], uint32_t a[4][4],
                                          uint32_t b[4][4]) {
#pragma unroll
    for (int mt = 0; mt < 4; mt++)
#pragma unroll
        for (int nb = 0; nb < 4; nb++) {
            mma_f16(c[mt][nb * 2 + 0], a[mt], b[nb][0], b[nb][1]);
            mma_f16(c[mt][nb * 2 + 1], a[mt], b[nb][2], b[nb][3]);
        }
}

__global__ void __launch_bounds__(THREADS, 2) gemm_f16_kernel(const float* __restrict__ bias,
                                                              float* __restrict__ out) {
    extern __shared__ char smem[];
    uint32_t sb = (smem_u32(smem) + 1023u) & ~1023u;
    uint32_t a_smem = sb;
    uint32_t b_smem = sb + 4 * A_SUB;

    int tid = threadIdx.x;
    int lane = tid & 31, wid = tid >> 5;
    int warpN = wid;               // 4 warps along N, 1 along M
    int q = lane >> 3, rl = lane & 7;

    int grid = gridDim.x;
    int t = blockIdx.x;
    if (t >= N_TILES) return;

    int m0, n0;
    tile_coords(t, m0, n0);
    int tn = t + grid;
    int m1 = 0, n1 = 0;
    if (tn < N_TILES) tile_coords(tn, m1, n1);

    int my_tiles = (N_TILES - 1 - t) / grid + 1;
    int total_gi = my_tiles * KITERS;            // multiple of 64 (even)

    // ldmatrix lane address decomposition (b16, k16 step = 32 bytes)
    uint32_t xorv = (uint32_t)rl << 4;
    uint32_t arow0 = (uint32_t)((q & 1) * 8 + rl);
    uint32_t acolq = (uint32_t)((q >> 1) * 16);
    uint32_t brow0 = (uint32_t)(warpN * 64 + (q >> 1) * 8 + rl);
    uint32_t bcolq = (uint32_t)((q & 1) * 16);

    float c[4][8][4];
#pragma unroll
    for (int i = 0; i < 4; i++)
#pragma unroll
        for (int j = 0; j < 8; j++)
#pragma unroll
            for (int k = 0; k < 4; k++) c[i][j][k] = 0.0f;

    // prologue: B(0) group, then A chunk {0,1} group
    load_B_part(g_wh + (size_t)n0 * K_TOTAL, b_smem, wid, lane, 0, 16);
    cp_commit();
    load_A(0, 0, m0, a_smem, tid);
    load_A(1, 1, m0, a_smem, tid);
    cp_commit();

    int g = lane >> 2, tig = lane & 3;   // epilogue decomposition

#pragma unroll 1
    for (int gi = 0; gi < total_gi; gi++) {
        int k = gi & (KITERS - 1);
        bool odd = (gi & 1) != 0;
        bool last_in_tile = (k == KITERS - 1);
        bool have_next = (gi + 1 < total_gi);
        uint32_t abase = a_smem + (gi & 3) * A_SUB;
        uint32_t bbase = b_smem + (gi & 1) * B_STAGE;

        // next-kiter load targets
        int kn = (k + 1) & (KITERS - 1);
        int ln0 = last_in_tile ? n1 : n0;
        int lm0 = last_in_tile ? m1 : m0;
        const __half* bsrc = g_wh + (size_t)ln0 * K_TOTAL + kn * BK;
        uint32_t bdst = b_smem + ((gi + 1) & 1) * B_STAGE;
        int suba = (gi + 1) & 3;                   // even at odd gi: 0 or 2

        // ---- single wait: drains everything committed during gi-1 ----
        cp_wait<0>();
        __syncwarp();               // my warp's B(gi) slice + A data resident

        uint32_t fa[2][4][4], fb[2][4][4];

        // B ks=0 fragments (warp-private; ahead of the CTA barrier)
        {
            uint32_t colB = bcolq ^ xorv;
#pragma unroll
            for (int nb = 0; nb < 4; nb++)
                ldsm4(fb[0][nb], bbase + (brow0 + nb * 16) * 128 + colB);
        }

        // CTA barrier only at even gi: certifies A chunk {gi, gi+1} ready
        // and A subs written at gi+1 free (readers done >=2 gis ago).
        if (!odd) __syncthreads();

        {
            uint32_t colA = acolq ^ xorv;
#pragma unroll
            for (int mt = 0; mt < 4; mt++)
                ldsm4(fa[0][mt], abase + (arow0 + mt * 16) * 128 + colA);
        }

        // ---- ks=0: loads fragment 1, then MMA ----
        if (have_next) {
            load_B_part(bsrc, bdst, wid, lane, 0, 6);
            if (odd) load_A(kn, suba, lm0, a_smem, tid);       // 4 cp16
        }
        mma_phase(c, fa[0], fb[0]);

        // ---- ks=1 ----
        ldsm_phase(fa[1], fb[1], abase, bbase, 1, arow0, acolq, brow0, bcolq, xorv);
        if (have_next) {
            load_B_part(bsrc, bdst, wid, lane, 6, 11);
            if (odd) load_A(kn + 1, suba + 1, lm0, a_smem, tid); // 4 cp16
        }
        mma_phase(c, fa[1], fb[1]);

        // ---- ks=2 ----
        ldsm_phase(fa[0], fb[0], abase, bbase, 2, arow0, acolq, brow0, bcolq, xorv);
        if (have_next) load_B_part(bsrc, bdst, wid, lane, 11, 16);
        mma_phase(c, fa[0], fb[0]);

        // ---- ks=3 (no loads; last chunk gets a full phase of flight) ----
        ldsm_phase(fa[1], fb[1], abase, bbase, 3, arow0, acolq, brow0, bcolq, xorv);
        mma_phase(c, fa[1], fb[1]);

        cp_commit();                // one group per kiter (possibly empty)

        // ---- tile epilogue: overlaps next tile's in-flight loads ----
        if (last_in_tile) {
#pragma unroll
            for (int nt = 0; nt < 8; nt++) {
                int col = n0 + warpN * 64 + nt * 8 + tig * 2;
                float bx = __ldg(bias + col);
                float by = __ldg(bias + col + 1);
#pragma unroll
                for (int mt = 0; mt < 4; mt++) {
                    size_t row = (size_t)m0 + mt * 16 + g;
                    float2 v0 = make_float2(c[mt][nt][0] + bx, c[mt][nt][1] + by);
                    float2 v1 = make_float2(c[mt][nt][2] + bx, c[mt][nt][3] + by);
                    *reinterpret_cast<float2*>(out + row * N_TOTAL + col) = v0;
                    *reinterpret_cast<float2*>(out + (row + 8) * N_TOTAL + col) = v1;
                    c[mt][nt][0] = 0.0f; c[mt][nt][1] = 0.0f;
                    c[mt][nt][2] = 0.0f; c[mt][nt][3] = 0.0f;
                }
            }
            m0 = m1; n0 = n1;
            tn += grid;
            if (tn < N_TILES) tile_coords(tn, m1, n1);
        }
    }
}

// ---------------------------------------------------------------------------
// Launch
// ---------------------------------------------------------------------------
extern "C" void kernel_launch(void* const* d_in, const int* in_sizes, int n_in,
                              void* d_out, int out_size) {
    const float* x = nullptr;
    const int* wq = nullptr;
    const float* ws = nullptr;
    const float* bias = nullptr;
    for (int i = 0; i < n_in; i++) {
        switch (in_sizes[i]) {
            case 33554432: x    = (const float*)d_in[i]; break;  // 4*2048*4096
            case 45088768: wq   = (const int*)d_in[i];   break;  // 11008*4096
            case 352256:   ws   = (const float*)d_in[i]; break;  // groups
            case 11008:    bias = (const float*)d_in[i]; break;
        }
    }

    cudaFuncSetAttribute(gemm_f16_kernel,
                         cudaFuncAttributeMaxDynamicSharedMemorySize, SMEM_BYTES);

    int dev = 0, sms = 148;
    cudaGetDevice(&dev);
    cudaDeviceGetAttribute(&sms, cudaDevAttrMultiProcessorCount, dev);

    prepass_kernel<<<X_BLOCKS + W_BLOCKS, 256>>>(x, wq, ws);   // 76800 blocks

    int grid = 2 * sms;                        // persistent: 2 CTAs per SM
    if (grid > N_TILES) grid = N_TILES;
    gemm_f16_kernel<<<grid, THREADS, SMEM_BYTES>>>(bias, (float*)d_out);
    (void)out_size;
}

// round 13
// speedup vs baseline: 1.1408x; 1.1408x over previous
#include <cuda_runtime.h>
#include <cuda_fp16.h>
#include <cstdint>

// ---------------------------------------------------------------------------
// Problem constants
// ---------------------------------------------------------------------------
static constexpr int M_TOTAL = 8192;      // 4 * 2048
static constexpr int N_TOTAL = 11008;
static constexpr int K_TOTAL = 4096;

static constexpr int BM = 64;
static constexpr int BN = 256;
static constexpr int BK = 64;                 // fp16 -> 128 B per row
static constexpr int KITERS = K_TOTAL / BK;   // 64 (even -> A chunks never straddle tiles)
static constexpr int THREADS = 128;           // 4 warps, 2 CTAs per SM

static constexpr int A_SUB = BM * BK * 2;     // 8 KB per kiter sub-buffer
static constexpr int B_STAGE = BN * BK * 2;   // 32 KB
static constexpr int SMEM_BYTES = 4 * A_SUB + 2 * B_STAGE + 1024;  // 99328 -> 2 CTAs/SM

static constexpr int PID_N = N_TOTAL / BN;    // 43
static constexpr int GROUP_M = 16;            // CTA raster group (wave set ~46MB < L2)
static constexpr int N_TILES = (M_TOTAL / BM) * PID_N;   // 5504

// prepass: 2 x 16B units per thread (MLP) -> fewer blocks, higher DRAM util
static constexpr int X_UNITS = 33554432 / 4;          // 8388608 float4
static constexpr int W_UNITS = 45088768 / 4;          // 11272192 int4
static constexpr int X_BLOCKS = X_UNITS / 2 / 256;    // 16384
static constexpr int W_BLOCKS = W_UNITS / 2 / 256;    // 22016

// ---------------------------------------------------------------------------
// Scratch (device globals: allocation-free)
// ---------------------------------------------------------------------------
__device__ __half g_xh[(size_t)M_TOTAL * K_TOTAL];   // 67 MB, fp16 x
__device__ __half g_wh[(size_t)N_TOTAL * K_TOTAL];   // 90 MB, fp16 dequant W

__constant__ float c_nf4[16] = {
    -1.0f, -0.6961928009986877f, -0.5250730514526367f, -0.39491748809814453f,
    -0.28444138169288635f, -0.18477343022823334f, -0.09105003625154495f, 0.0f,
    0.07958029955625534f, 0.16093020141124725f, 0.24611230194568634f,
    0.33791524171829224f, 0.44070982933044434f, 0.5626170039176941f,
    0.7229568362236023f, 1.0f};

// ---------------------------------------------------------------------------
// Helpers (baseline PTX only; sm_103 virtual target has no tcgen05)
// ---------------------------------------------------------------------------
__device__ __forceinline__ uint32_t smem_u32(const void* p) {
    uint32_t a;
    asm("{ .reg .u64 t; cvta.to.shared.u64 t, %1; cvt.u32.u64 %0, t; }" : "=r"(a) : "l"(p));
    return a;
}

__device__ __forceinline__ void cp16(uint32_t dst, const void* src) {
    asm volatile("cp.async.cg.shared.global [%0], [%1], 16;" :: "r"(dst), "l"(src));
}
__device__ __forceinline__ void cp_commit() {
    asm volatile("cp.async.commit_group;" ::: "memory");
}
template <int N>
__device__ __forceinline__ void cp_wait() {
    asm volatile("cp.async.wait_group %0;" :: "n"(N) : "memory");
}

__device__ __forceinline__ void ldsm4(uint32_t* r, uint32_t addr) {
    asm volatile("ldmatrix.sync.aligned.m8n8.x4.shared.b16 {%0,%1,%2,%3}, [%4];"
                 : "=r"(r[0]), "=r"(r[1]), "=r"(r[2]), "=r"(r[3]) : "r"(addr));
}

__device__ __forceinline__ void mma_f16(float* c, const uint32_t* a,
                                        uint32_t b0, uint32_t b1) {
    asm volatile(
        "mma.sync.aligned.m16n8k16.row.col.f32.f16.f16.f32 "
        "{%0,%1,%2,%3}, {%4,%5,%6,%7}, {%8,%9}, {%0,%1,%2,%3};"
        : "+f"(c[0]), "+f"(c[1]), "+f"(c[2]), "+f"(c[3])
        : "r"(a[0]), "r"(a[1]), "r"(a[2]), "r"(a[3]), "r"(b0), "r"(b1));
}

// SW128 swizzle on (row*128 + colb)
#define SWZ(row, colb) ((uint32_t)(row) * 128u + ((uint32_t)(colb) ^ ((((uint32_t)(row)) & 7u) << 4)))

// grouped rasterization: GROUP_M m-tiles share each B n-column within a wave
__device__ __forceinline__ void tile_coords(int t, int& m0, int& n0) {
    int group = t / (GROUP_M * PID_N);
    int local = t % (GROUP_M * PID_N);
    int pid_m = group * GROUP_M + (local & (GROUP_M - 1));
    int pid_n = local >> 4;                    // GROUP_M = 16
    m0 = pid_m * BM;
    n0 = pid_n * BN;
}

// ---------------------------------------------------------------------------
// Kernel 1 (fused prepass): x -> fp16, NF4 dequant W -> fp16.  2 units/thread.
// ---------------------------------------------------------------------------
__global__ void __launch_bounds__(256) prepass_kernel(const float* __restrict__ x,
                                                      const int* __restrict__ q,
                                                      const float* __restrict__ sc) {
    if (blockIdx.x < X_BLOCKS) {
        size_t i = ((size_t)blockIdx.x * 256 + threadIdx.x) * 2;   // float4 index
        float4 v0 = reinterpret_cast<const float4*>(x)[i];
        float4 v1 = reinterpret_cast<const float4*>(x)[i + 1];
        __half2 a0 = __floats2half2_rn(v0.x, v0.y);
        __half2 a1 = __floats2half2_rn(v0.z, v0.w);
        __half2 a2 = __floats2half2_rn(v1.x, v1.y);
        __half2 a3 = __floats2half2_rn(v1.z, v1.w);
        uint4 o = make_uint4(*reinterpret_cast<uint32_t*>(&a0),
                             *reinterpret_cast<uint32_t*>(&a1),
                             *reinterpret_cast<uint32_t*>(&a2),
                             *reinterpret_cast<uint32_t*>(&a3));
        reinterpret_cast<uint4*>(g_xh)[i >> 1] = o;
    } else {
        float tv = c_nf4[threadIdx.x & 15];                  // lane l holds nf4[l&15]
        size_t i = ((size_t)(blockIdx.x - X_BLOCKS) * 256 + threadIdx.x) * 2; // int4 idx
        int4 q0 = reinterpret_cast<const int4*>(q)[i];
        int4 q1 = reinterpret_cast<const int4*>(q)[i + 1];
        float s = __ldg(sc + (i >> 5));      // packs 2j,2j+1 share the 128-elem group
        float w0 = __shfl_sync(0xffffffffu, tv, q0.x & 15) * s;
        float w1 = __shfl_sync(0xffffffffu, tv, q0.y & 15) * s;
        float w2 = __shfl_sync(0xffffffffu, tv, q0.z & 15) * s;
        float w3 = __shfl_sync(0xffffffffu, tv, q0.w & 15) * s;
        float w4 = __shfl_sync(0xffffffffu, tv, q1.x & 15) * s;
        float w5 = __shfl_sync(0xffffffffu, tv, q1.y & 15) * s;
        float w6 = __shfl_sync(0xffffffffu, tv, q1.z & 15) * s;
        float w7 = __shfl_sync(0xffffffffu, tv, q1.w & 15) * s;
        __half2 a0 = __floats2half2_rn(w0, w1);
        __half2 a1 = __floats2half2_rn(w2, w3);
        __half2 a2 = __floats2half2_rn(w4, w5);
        __half2 a3 = __floats2half2_rn(w6, w7);
        uint4 o = make_uint4(*reinterpret_cast<uint32_t*>(&a0),
                             *reinterpret_cast<uint32_t*>(&a1),
                             *reinterpret_cast<uint32_t*>(&a2),
                             *reinterpret_cast<uint32_t*>(&a3));
        reinterpret_cast<uint4*>(g_wh)[i >> 1] = o;
    }
}

// ---------------------------------------------------------------------------
// Kernel 2: persistent mma.sync fp16 GEMM (R8 structure, verbatim inner loop).
// 128 threads = 4 warps, warp tile 64x64 (1M x 4N), 2 CTAs per SM.
// A: 4 sub-buffers in 2-kiter chunks -> __syncthreads at even gi only.
// B: 2 warp-private stages.  Single cp_wait<0> per kiter.
// ---------------------------------------------------------------------------
__device__ __forceinline__ void load_A(int kiter, int sub, int m0,
                                       uint32_t a_smem, int tid) {
    const __half* asrc = g_xh + (size_t)m0 * K_TOTAL + kiter * BK;
    uint32_t adst = a_smem + sub * A_SUB;
#pragma unroll
    for (int it = 0; it < 4; it++) {                 // 512 16B chunks / 128 thr
        int idx = tid + it * THREADS;
        int r = idx >> 3, ch = idx & 7;
        cp16(adst + SWZ(r, ch * 16), asrc + (size_t)r * K_TOTAL + ch * 8);
    }
}

// warp-sliced: warp w loads (and later reads) only B rows [64w, 64w+64)
__device__ __forceinline__ void load_B(int kiter, int s, int n0,
                                       uint32_t b_smem, int wid, int lane) {
    const __half* bsrc = g_wh + (size_t)n0 * K_TOTAL + kiter * BK;
    uint32_t bdst = b_smem + s * B_STAGE;
#pragma unroll
    for (int it = 0; it < 16; it++) {                // 512 chunks / 32 lanes
        int c = lane + it * 32;
        int r = wid * 64 + (c >> 3), ch = c & 7;
        cp16(bdst + SWZ(r, ch * 16), bsrc + (size_t)r * K_TOTAL + ch * 8);
    }
}

__global__ void __launch_bounds__(THREADS, 2) gemm_f16_kernel(const float* __restrict__ bias,
                                                              float* __restrict__ out) {
    extern __shared__ char smem[];
    uint32_t sb = (smem_u32(smem) + 1023u) & ~1023u;
    uint32_t a_smem = sb;
    uint32_t b_smem = sb + 4 * A_SUB;

    int tid = threadIdx.x;
    int lane = tid & 31, wid = tid >> 5;
    int warpN = wid;               // 4 warps along N, 1 along M
    int q = lane >> 3, rl = lane & 7;

    int grid = gridDim.x;
    int t = blockIdx.x;
    if (t >= N_TILES) return;

    int m0, n0;
    tile_coords(t, m0, n0);
    int tn = t + grid;
    int m1 = 0, n1 = 0;
    if (tn < N_TILES) tile_coords(tn, m1, n1);

    int my_tiles = (N_TILES - 1 - t) / grid + 1;
    int total_gi = my_tiles * KITERS;            // multiple of 64 (even)

    // ldmatrix lane address decomposition (b16, k16 step = 32 bytes)
    uint32_t xorv = (uint32_t)rl << 4;
    uint32_t arow0 = (uint32_t)((q & 1) * 8 + rl);
    uint32_t acolq = (uint32_t)((q >> 1) * 16);
    uint32_t brow0 = (uint32_t)(warpN * 64 + (q >> 1) * 8 + rl);
    uint32_t bcolq = (uint32_t)((q & 1) * 16);

    float c[4][8][4];
#pragma unroll
    for (int i = 0; i < 4; i++)
#pragma unroll
        for (int j = 0; j < 8; j++)
#pragma unroll
            for (int k = 0; k < 4; k++) c[i][j][k] = 0.0f;

    // prologue: B(0) group, then A chunk {0,1} group -> pending = both at gi=0
    load_B(0, 0, n0, b_smem, wid, lane);
    cp_commit();
    load_A(0, 0, m0, a_smem, tid);
    load_A(1, 1, m0, a_smem, tid);
    cp_commit();

    int g = lane >> 2, tig = lane & 3;   // epilogue decomposition

#pragma unroll 1
    for (int gi = 0; gi < total_gi; gi++) {
        int k = gi & (KITERS - 1);
        int sub = gi & 3;
        int sbb = gi & 1;
        bool odd = (gi & 1) != 0;
        bool last_in_tile = (k == KITERS - 1);
        bool have_next = (gi + 1 < total_gi);
        uint32_t abase = a_smem + sub * A_SUB;
        uint32_t bbase = b_smem + sbb * B_STAGE;

        // ---- single wait: drains everything committed during gi-1 ----
        cp_wait<0>();
        __syncwarp();               // my warp's B(gi) slice + A data (own) resident

        // B phase (warp-private; ahead of the CTA barrier)
        uint32_t b0[4][4];
        {
            uint32_t colB = bcolq ^ xorv;
#pragma unroll
            for (int nb = 0; nb < 4; nb++)
                ldsm4(b0[nb], bbase + (brow0 + nb * 16) * 128 + colB);
        }
        if (have_next) {
            int ln0 = last_in_tile ? n1 : n0;
            load_B((k + 1) & (KITERS - 1), (gi + 1) & 1, ln0, b_smem, wid, lane);
        }
        cp_commit();                // B(gi+1) group (possibly empty)

        // CTA barrier only at even gi: certifies A chunk {gi, gi+1} ready
        // and A subs written at gi+1 free (readers done >=2 gis ago).
        if (!odd) __syncthreads();

        // A ks=0 fragments, then (odd gi) issue next A chunk
        uint32_t a0[4][4];
        {
            uint32_t colA = acolq ^ xorv;
#pragma unroll
            for (int mt = 0; mt < 4; mt++)
                ldsm4(a0[mt], abase + (arow0 + mt * 16) * 128 + colA);
        }
        if (odd && have_next) {
            // chunk covers flat gi+1, gi+2 (same tile: k'=k+1 even <= 62)
            int lm0 = last_in_tile ? m1 : m0;
            int kk = (k + 1) & (KITERS - 1);
            int sub2 = (gi + 1) & 3;            // even: {0,1} or {2,3}
            load_A(kk, sub2, lm0, a_smem, tid);
            load_A(kk + 1, sub2 + 1, lm0, a_smem, tid);
        }
        cp_commit();                // A group (possibly empty)

        // ---- ks = 0 (both operands prefetched) ----
#pragma unroll
        for (int mt = 0; mt < 4; mt++)
#pragma unroll
            for (int nb = 0; nb < 4; nb++) {
                mma_f16(c[mt][nb * 2 + 0], a0[mt], b0[nb][0], b0[nb][1]);
                mma_f16(c[mt][nb * 2 + 1], a0[mt], b0[nb][2], b0[nb][3]);
            }
        // ---- ks = 1..3 ----
#pragma unroll
        for (int ks = 1; ks < 4; ks++) {
            uint32_t colA = ((uint32_t)(ks * 32) + acolq) ^ xorv;
            uint32_t colB = ((uint32_t)(ks * 32) + bcolq) ^ xorv;
            uint32_t a[4][4], b[4][4];
#pragma unroll
            for (int mt = 0; mt < 4; mt++)
                ldsm4(a[mt], abase + (arow0 + mt * 16) * 128 + colA);
#pragma unroll
            for (int nb = 0; nb < 4; nb++)
                ldsm4(b[nb], bbase + (brow0 + nb * 16) * 128 + colB);
#pragma unroll
            for (int mt = 0; mt < 4; mt++)
#pragma unroll
                for (int nb = 0; nb < 4; nb++) {
                    mma_f16(c[mt][nb * 2 + 0], a[mt], b[nb][0], b[nb][1]);
                    mma_f16(c[mt][nb * 2 + 1], a[mt], b[nb][2], b[nb][3]);
                }
        }

        // ---- tile epilogue: streaming stores (keep output out of L2) ----
        if (last_in_tile) {
#pragma unroll
            for (int nt = 0; nt < 8; nt++) {
                int col = n0 + warpN * 64 + nt * 8 + tig * 2;
                float bx = __ldg(bias + col);
                float by = __ldg(bias + col + 1);
#pragma unroll
                for (int mt = 0; mt < 4; mt++) {
                    size_t row = (size_t)m0 + mt * 16 + g;
                    float2 v0 = make_float2(c[mt][nt][0] + bx, c[mt][nt][1] + by);
                    float2 v1 = make_float2(c[mt][nt][2] + bx, c[mt][nt][3] + by);
                    __stcs(reinterpret_cast<float2*>(out + row * N_TOTAL + col), v0);
                    __stcs(reinterpret_cast<float2*>(out + (row + 8) * N_TOTAL + col), v1);
                    c[mt][nt][0] = 0.0f; c[mt][nt][1] = 0.0f;
                    c[mt][nt][2] = 0.0f; c[mt][nt][3] = 0.0f;
                }
            }
            m0 = m1; n0 = n1;
            tn += grid;
            if (tn < N_TILES) tile_coords(tn, m1, n1);
        }
    }
}

// ---------------------------------------------------------------------------
// Launch
// ---------------------------------------------------------------------------
extern "C" void kernel_launch(void* const* d_in, const int* in_sizes, int n_in,
                              void* d_out, int out_size) {
    const float* x = nullptr;
    const int* wq = nullptr;
    const float* ws = nullptr;
    const float* bias = nullptr;
    for (int i = 0; i < n_in; i++) {
        switch (in_sizes[i]) {
            case 33554432: x    = (const float*)d_in[i]; break;  // 4*2048*4096
            case 45088768: wq   = (const int*)d_in[i];   break;  // 11008*4096
            case 352256:   ws   = (const float*)d_in[i]; break;  // groups
            case 11008:    bias = (const float*)d_in[i]; break;
        }
    }

    cudaFuncSetAttribute(gemm_f16_kernel,
                         cudaFuncAttributeMaxDynamicSharedMemorySize, SMEM_BYTES);

    int dev = 0, sms = 148;
    cudaGetDevice(&dev);
    cudaDeviceGetAttribute(&sms, cudaDevAttrMultiProcessorCount, dev);

    prepass_kernel<<<X_BLOCKS + W_BLOCKS, 256>>>(x, wq, ws);   // 38400 blocks

    int grid = 2 * sms;                        // persistent: 2 CTAs per SM
    if (grid > N_TILES) grid = N_TILES;
    gemm_f16_kernel<<<grid, THREADS, SMEM_BYTES>>>(bias, (float*)d_out);
    (void)out_size;
}